// round 13
// baseline (speedup 1.0000x reference)
#include <cuda_runtime.h>
#include <cuda_fp16.h>
#include <cstdint>

#define DIN  1024
#define DH   512
#define NB   8192
#define DOUT 512

#define MROW 32
#define NCTA (NB / MROW)   // 256
#define NT   256           // 8 warps
#define NCHK 32            // K/16 chunks per matmul

// A (hh fp16) smem: 32 rows, pitch 1040B (65*16B -> ldmatrix conflict-free)
#define APITCH 1040
#define A_BYTES (MROW * APITCH)          // 33280
// B per-warp stages: 64 n-rows x 64B ([hi k16 | lo k16], 2-bit XOR seg swizzle)
#define BROW 64
#define BSTG (64 * BROW)                 // 4096 per stage
#define NBSTG 2
#define BWRP (NBSTG * BSTG)              // 8192 per warp
#define B_OFF A_BYTES                    // 33280
#define REC_SMEM (B_OFF + 8 * BWRP)      // 98816  (2 CTAs/SM: 197632 <= 227KB)

typedef unsigned long long ull;

// ---------------- device scratch ----------------
__device__ float g_sigma;
__device__ __align__(16) float g_Wet[DIN * DH];
__device__ __align__(16) float g_Wht[DH * DOUT];
__device__ __align__(16) float g_bcomb[DH];
__device__ __align__(16) float g_xe[NB * DH];    // x@We.T + be + bW
__device__ __align__(16) float g_hxe[NB * DH];   // h + xe
__device__ __align__(16) float g_h[NB * DH];     // outer state
__device__ __align__(16) __half g_whi[DH * DH];  // (W/sigma)[n][k] fp16 hi
__device__ __align__(16) __half g_wlo[DH * DH];  // fp16 residual lo

// ---------------- helpers ----------------
__device__ __forceinline__ uint32_t smem_u32(const void* p) {
    uint32_t a;
    asm("{ .reg .u64 t; cvta.to.shared.u64 t, %1; cvt.u32.u64 %0, t; }" : "=r"(a) : "l"(p));
    return a;
}
__device__ __forceinline__ void cp16(uint32_t dst, const void* src) {
    asm volatile("cp.async.cg.shared.global [%0], [%1], 16;" ::"r"(dst), "l"(src));
}
__device__ __forceinline__ void cp_commit() {
    asm volatile("cp.async.commit_group;" ::: "memory");
}
__device__ __forceinline__ void cp_wait1() {
    asm volatile("cp.async.wait_group 1;" ::: "memory");
}
__device__ __forceinline__ void ldsm4(uint32_t* r, uint32_t addr) {
    asm volatile("ldmatrix.sync.aligned.m8n8.x4.shared.b16 {%0,%1,%2,%3}, [%4];"
                 : "=r"(r[0]), "=r"(r[1]), "=r"(r[2]), "=r"(r[3])
                 : "r"(addr));
}
__device__ __forceinline__ void mma16816(float* d, const uint32_t* a, const uint32_t* b) {
    asm volatile(
        "mma.sync.aligned.m16n8k16.row.col.f32.f16.f16.f32 "
        "{%0,%1,%2,%3}, {%4,%5,%6,%7}, {%8,%9}, {%0,%1,%2,%3};"
        : "+f"(d[0]), "+f"(d[1]), "+f"(d[2]), "+f"(d[3])
        : "r"(a[0]), "r"(a[1]), "r"(a[2]), "r"(a[3]), "r"(b[0]), "r"(b[1]));
}
__device__ __forceinline__ float fast_tanh(float x) {
    float a = fabsf(x);
    float e = exp2f(-2.8853900817779268f * a);
    float r = __fdividef(1.0f - e, 1.0f + e);
    return copysignf(r, x);
}
__device__ __forceinline__ uint32_t pack_h2(float a, float b) {
    __half2 h = __floats2half2_rn(a, b);
    return *(uint32_t*)&h;
}
__device__ __forceinline__ float2 h2f(uint32_t u) {
    __half2 h = *(__half2*)&u;
    return __half22float2(h);
}

// ---------------- kernel 1: sigma ----------------
__global__ void k_sigma(const float* __restrict__ W, const float* __restrict__ u) {
    __shared__ float sv[DH];
    __shared__ float red[DH];
    int t = threadIdx.x;
    float acc = 0.f;
    for (int i = 0; i < DH; i++) acc += W[(size_t)i * DH + t] * u[i];
    sv[t] = acc;
    red[t] = acc * acc;
    __syncthreads();
    for (int s = 256; s > 0; s >>= 1) {
        if (t < s) red[t] += red[t + s];
        __syncthreads();
    }
    float inv1 = 1.f / (sqrtf(red[0]) + 1e-12f);
    __syncthreads();
    sv[t] *= inv1;
    __syncthreads();
    float sacc = 0.f;
    const float* wr = W + (size_t)t * DH;
    for (int j = 0; j < DH; j++) sacc += wr[j] * sv[j];
    red[t] = sacc * sacc;
    __syncthreads();
    for (int s = 256; s > 0; s >>= 1) {
        if (t < s) red[t] += red[t + s];
        __syncthreads();
    }
    if (t == 0) {
        float ss = red[0];
        g_sigma = ss / (sqrtf(ss) + 1e-12f);
    }
}

// ---------------- kernel 2: weight prep ----------------
__global__ void k_prep(const float* __restrict__ W, const float* __restrict__ We,
                       const float* __restrict__ Wh, const float* __restrict__ be,
                       const float* __restrict__ bW) {
    float inv = 1.0f / g_sigma;
    int stride = gridDim.x * blockDim.x;
    int t0 = blockIdx.x * blockDim.x + threadIdx.x;
    for (int idx = t0; idx < DH * DH; idx += stride) {
        float v = W[idx] * inv;
        __half hi = __float2half_rn(v);
        g_whi[idx] = hi;
        g_wlo[idx] = __float2half_rn(v - __half2float(hi));
    }
    for (int idx = t0; idx < DIN * DH; idx += stride) {
        int d = idx >> 9, j = idx & 511;
        g_Wet[idx] = We[(size_t)j * DIN + d];
    }
    for (int idx = t0; idx < DH * DOUT; idx += stride) {
        int k = idx / DOUT, o = idx - k * DOUT;
        g_Wht[idx] = Wh[(size_t)o * DH + k];
    }
    for (int idx = t0; idx < DH; idx += stride) g_bcomb[idx] = be[idx] + bW[idx];
}

// ---------------- generic tiled GEMM ----------------
__global__ __launch_bounds__(256) void k_gemm(const float* __restrict__ A,
                                              const float* __restrict__ Bt,
                                              const float* __restrict__ bias,
                                              float* __restrict__ C, int M, int N, int K) {
    __shared__ float As[16][64];
    __shared__ float Bs[16][64];
    int tid = threadIdx.x;
    int bx = blockIdx.x, by = blockIdx.y;
    int tx = tid & 15, ty = tid >> 4;
    float accv[4][4];
#pragma unroll
    for (int i = 0; i < 4; i++)
#pragma unroll
        for (int j = 0; j < 4; j++) accv[i][j] = 0.f;
    for (int k0 = 0; k0 < K; k0 += 16) {
        {
            int r = tid >> 2;
            int c = (tid & 3) * 4;
            float4 av = *(const float4*)&A[(size_t)(by * 64 + r) * K + k0 + c];
            As[c + 0][r] = av.x;
            As[c + 1][r] = av.y;
            As[c + 2][r] = av.z;
            As[c + 3][r] = av.w;
        }
        {
            int kr = tid >> 4;
            int c = (tid & 15) * 4;
            float4 bv = *(const float4*)&Bt[(size_t)(k0 + kr) * N + bx * 64 + c];
            *(float4*)&Bs[kr][c] = bv;
        }
        __syncthreads();
#pragma unroll
        for (int k = 0; k < 16; k++) {
            float a[4], b[4];
#pragma unroll
            for (int i = 0; i < 4; i++) a[i] = As[k][ty * 4 + i];
#pragma unroll
            for (int j = 0; j < 4; j++) b[j] = Bs[k][tx * 4 + j];
#pragma unroll
            for (int i = 0; i < 4; i++)
#pragma unroll
                for (int j = 0; j < 4; j++) accv[i][j] += a[i] * b[j];
        }
        __syncthreads();
    }
#pragma unroll
    for (int i = 0; i < 4; i++) {
        int m = by * 64 + ty * 4 + i;
#pragma unroll
        for (int j = 0; j < 4; j++) {
            int n = bx * 64 + tx * 4 + j;
            C[(size_t)m * N + n] = accv[i][j] + bias[n];
        }
    }
}

// ---------------- kernel 3: recurrent core (2 CTAs/SM, warp-private W pipe) ----------------
__global__ __launch_bounds__(NT, 2) void k_rec(const int* __restrict__ steps_p) {
    extern __shared__ char smem[];
    const uint32_t sb = smem_u32(smem);
    const int tid = threadIdx.x;
    const int w = tid >> 5, l = tid & 31;
    const int nb = w * 64;  // this warp's private n-range [nb, nb+64)
    const int row0 = blockIdx.x * MROW;
    const uint32_t bbase = sb + B_OFF + (uint32_t)w * BWRP;

    // linear mapping for elementwise phases: row lr (0..31), 64-col block lcb
    const int lr = tid >> 3;
    const int lcb = (tid & 7) * 64;
    const size_t lg = (size_t)(row0 + lr) * DH + lcb;
    const uint32_t la = (uint32_t)(lr * APITCH + lcb * 2);

    // W loader: lane l stages rows l and l+32 of the warp's 64-row slice
    const int r0l = l, r1l = l + 32;
    const __half* srch0 = g_whi + (size_t)(nb + r0l) * DH;
    const __half* srcl0 = g_wlo + (size_t)(nb + r0l) * DH;
    const __half* srch1 = g_whi + (size_t)(nb + r1l) * DH;
    const __half* srcl1 = g_wlo + (size_t)(nb + r1l) * DH;
    const int sw0 = (r0l >> 1) & 3, sw1 = (r1l >> 1) & 3;
    const uint32_t bd0 = (uint32_t)(r0l * BROW), bd1 = (uint32_t)(r1l * BROW);

    // init: h = 0, hxe = xe
#pragma unroll
    for (int q = 0; q < 16; q++) {
        float4 xv = *(const float4*)(g_xe + lg + 4 * q);
        *(float4*)(g_hxe + lg + 4 * q) = xv;
        *(float4*)(g_h + lg + 4 * q) = make_float4(0.f, 0.f, 0.f, 0.f);
    }

    const int steps = steps_p[0];

    for (int s = 0; s < steps; s++) {
        // ---- inner iter 0: hh = 0.5*tanh(hxe) -> smem fp16 ----
#pragma unroll
        for (int q = 0; q < 16; q++) {
            float4 xv = *(const float4*)(g_hxe + lg + 4 * q);
            uint2 hp;
            hp.x = pack_h2(0.5f * fast_tanh(xv.x), 0.5f * fast_tanh(xv.y));
            hp.y = pack_h2(0.5f * fast_tanh(xv.z), 0.5f * fast_tanh(xv.w));
            *(uint2*)(smem + la + 8 * q) = hp;
        }
        __syncthreads();

        // ---- inner iters 1..4 ----
        for (int it = 1; it < 5; it++) {
            float acc[2][8][4];
#pragma unroll
            for (int mt = 0; mt < 2; mt++)
#pragma unroll
                for (int nt = 0; nt < 8; nt++)
#pragma unroll
                    for (int e = 0; e < 4; e++) acc[mt][nt][e] = 0.f;

            // prologue: chunks 0,1 into stages 0,1 (warp-private)
#pragma unroll
            for (int c0 = 0; c0 < 2; c0++) {
                uint32_t st = bbase + (uint32_t)c0 * BSTG;
                cp16(st + bd0 + ((0 ^ sw0) << 4), srch0 + c0 * 16);
                cp16(st + bd0 + ((1 ^ sw0) << 4), srch0 + c0 * 16 + 8);
                cp16(st + bd0 + ((2 ^ sw0) << 4), srcl0 + c0 * 16);
                cp16(st + bd0 + ((3 ^ sw0) << 4), srcl0 + c0 * 16 + 8);
                cp16(st + bd1 + ((0 ^ sw1) << 4), srch1 + c0 * 16);
                cp16(st + bd1 + ((1 ^ sw1) << 4), srch1 + c0 * 16 + 8);
                cp16(st + bd1 + ((2 ^ sw1) << 4), srcl1 + c0 * 16);
                cp16(st + bd1 + ((3 ^ sw1) << 4), srcl1 + c0 * 16 + 8);
                cp_commit();
            }

            for (int c = 0; c < NCHK; c++) {
                cp_wait1();  // own chunk c resident (warp-local)
                const uint32_t stg = bbase + (uint32_t)(c & 1) * BSTG;
                // A fragments: rows mt*16, k = c*16
                uint32_t ah[2][4];
#pragma unroll
                for (int mt = 0; mt < 2; mt++) {
                    uint32_t ao = (uint32_t)((mt * 16 + (l & 15)) * APITCH + c * 32 +
                                             (l >> 4) * 16);
                    ldsm4(ah[mt], sb + ao);
                }
#pragma unroll
                for (int g2 = 0; g2 < 4; g2++) {  // n16 groups
                    int br = g2 * 16 + (l & 7) + 8 * (l >> 4);
                    int sl = (l >> 3) & 1;
                    int bsw = (br >> 1) & 3;
                    uint32_t rowb = stg + (uint32_t)(br * BROW);
                    uint32_t bh[4], bl[4];
                    ldsm4(bh, rowb + (uint32_t)(((sl) ^ bsw) << 4));
                    ldsm4(bl, rowb + (uint32_t)(((sl + 2) ^ bsw) << 4));
#pragma unroll
                    for (int mt = 0; mt < 2; mt++) {
                        mma16816(acc[mt][2 * g2 + 0], ah[mt], bh + 0);
                        mma16816(acc[mt][2 * g2 + 1], ah[mt], bh + 2);
                        mma16816(acc[mt][2 * g2 + 0], ah[mt], bl + 0);
                        mma16816(acc[mt][2 * g2 + 1], ah[mt], bl + 2);
                    }
                }
                // refill chunk c+2 into stage (c&1) AFTER reads (program order safe)
                {
                    int c2 = c + 2;
                    if (c2 < NCHK) {
                        uint32_t st = bbase + (uint32_t)(c & 1) * BSTG;
                        cp16(st + bd0 + ((0 ^ sw0) << 4), srch0 + c2 * 16);
                        cp16(st + bd0 + ((1 ^ sw0) << 4), srch0 + c2 * 16 + 8);
                        cp16(st + bd0 + ((2 ^ sw0) << 4), srcl0 + c2 * 16);
                        cp16(st + bd0 + ((3 ^ sw0) << 4), srcl0 + c2 * 16 + 8);
                        cp16(st + bd1 + ((0 ^ sw1) << 4), srch1 + c2 * 16);
                        cp16(st + bd1 + ((1 ^ sw1) << 4), srch1 + c2 * 16 + 8);
                        cp16(st + bd1 + ((2 ^ sw1) << 4), srcl1 + c2 * 16);
                        cp16(st + bd1 + ((3 ^ sw1) << 4), srcl1 + c2 * 16 + 8);
                    }
                    cp_commit();  // uniform group arithmetic
                }
            }
            __syncthreads();  // all A-smem reads done before epilogue writes

            // ---- epilogue: hh = 0.5*hh_old + 0.5*tanh(acc + hxe) ----
#pragma unroll
            for (int mt = 0; mt < 2; mt++) {
                int ra = mt * 16 + (l >> 2);
#pragma unroll
                for (int half = 0; half < 2; half++) {
                    int r = ra + 8 * half;
                    const size_t gr = (size_t)(row0 + r) * DH;
                    uint32_t aoff = (uint32_t)(r * APITCH);
#pragma unroll
                    for (int nt = 0; nt < 8; nt++) {
                        int col = nb + nt * 8 + 2 * (l & 3);
                        uint32_t hu = *(uint32_t*)(smem + aoff + col * 2);
                        float2 hf = h2f(hu);
                        float2 xe2 = *(const float2*)(g_hxe + gr + col);
                        float a0 = acc[mt][nt][2 * half + 0];
                        float a1 = acc[mt][nt][2 * half + 1];
                        float v0 = 0.5f * hf.x + 0.5f * fast_tanh(a0 + xe2.x);
                        float v1 = 0.5f * hf.y + 0.5f * fast_tanh(a1 + xe2.y);
                        *(uint32_t*)(smem + aoff + col * 2) = pack_h2(v0, v1);
                    }
                }
            }
            __syncthreads();
        }

        // ---- outer update: h = 0.5h + 0.5hh ; hxe = h + xe ----
#pragma unroll
        for (int q = 0; q < 16; q++) {
            uint2 hp = *(uint2*)(smem + la + 8 * q);
            float2 h0 = h2f(hp.x), h1 = h2f(hp.y);
            float4 hv = *(const float4*)(g_h + lg + 4 * q);
            float4 xv = *(const float4*)(g_xe + lg + 4 * q);
            float4 hn;
            hn.x = 0.5f * hv.x + 0.5f * h0.x;
            hn.y = 0.5f * hv.y + 0.5f * h0.y;
            hn.z = 0.5f * hv.z + 0.5f * h1.x;
            hn.w = 0.5f * hv.w + 0.5f * h1.y;
            *(float4*)(g_h + lg + 4 * q) = hn;
            float4 hx;
            hx.x = hn.x + xv.x;
            hx.y = hn.y + xv.y;
            hx.z = hn.z + xv.z;
            hx.w = hn.w + xv.w;
            *(float4*)(g_hxe + lg + 4 * q) = hx;
        }
        __syncthreads();
    }
}

// ---------------- launch ----------------
extern "C" void kernel_launch(void* const* d_in, const int* in_sizes, int n_in, void* d_out,
                              int out_size) {
    const float* x = (const float*)d_in[0];
    const float* We = (const float*)d_in[1];
    const float* be = (const float*)d_in[2];
    const float* W = (const float*)d_in[3];
    const float* bW = (const float*)d_in[4];
    const float* u = (const float*)d_in[5];
    const float* Wh = (const float*)d_in[6];
    const float* bh = (const float*)d_in[7];
    const int* steps = (const int*)d_in[8];
    float* out = (float*)d_out;

    float *p_Wet, *p_Wht, *p_xe, *p_h, *p_bcomb;
    cudaGetSymbolAddress((void**)&p_Wet, g_Wet);
    cudaGetSymbolAddress((void**)&p_Wht, g_Wht);
    cudaGetSymbolAddress((void**)&p_xe, g_xe);
    cudaGetSymbolAddress((void**)&p_h, g_h);
    cudaGetSymbolAddress((void**)&p_bcomb, g_bcomb);

    cudaFuncSetAttribute(k_rec, cudaFuncAttributeMaxDynamicSharedMemorySize, REC_SMEM);

    k_sigma<<<1, 512>>>(W, u);
    k_prep<<<512, 256>>>(W, We, Wh, be, bW);

    dim3 g1(DH / 64, NB / 64);
    k_gemm<<<g1, 256>>>(x, p_Wet, p_bcomb, p_xe, NB, DH, DIN);

    k_rec<<<NCTA, NT, REC_SMEM>>>(steps);

    dim3 g2(DOUT / 64, NB / 64);
    k_gemm<<<g2, 256>>>(p_h, p_Wht, bh, out, NB, DOUT, DH);
}

// round 14
// speedup vs baseline: 1.0003x; 1.0003x over previous
#include <cuda_runtime.h>
#include <cuda_fp16.h>
#include <cstdint>

#define DIN  1024
#define DH   512
#define NB   8192
#define DOUT 512

#define MROW 32
#define NCTA (NB / MROW)   // 256
#define NT   256           // 8 warps
#define NCHK 32            // K/16 chunks per matmul

// A (hh fp16) smem: 32 rows, pitch 1040B (65*16B -> ldmatrix conflict-free)
#define APITCH 1040
#define A_BYTES (MROW * APITCH)          // 33280
// B per-warp stages: 64 n-rows x 64B ([hi k16 | lo k16], 2-bit XOR seg swizzle)
#define BROW 64
#define BSTG (64 * BROW)                 // 4096 per stage
#define NBSTG 2
#define BWRP (NBSTG * BSTG)              // 8192 per warp
#define B_OFF A_BYTES                    // 33280
#define REC_SMEM (B_OFF + 8 * BWRP)      // 98816  (2 CTAs/SM: 197632 <= 227KB)

typedef unsigned long long ull;

// ---------------- device scratch ----------------
__device__ float g_sigma;
__device__ __align__(16) float g_Wet[DIN * DH];
__device__ __align__(16) float g_Wht[DH * DOUT];
__device__ __align__(16) float g_bcomb[DH];
__device__ __align__(16) float g_xe[NB * DH];    // x@We.T + be + bW
__device__ __align__(16) float g_hxe[NB * DH];   // h + xe
__device__ __align__(16) float g_h[NB * DH];     // outer state
__device__ __align__(16) __half g_whi[DH * DH];  // (W/sigma)[n][k] fp16 hi
__device__ __align__(16) __half g_wlo[DH * DH];  // fp16 residual lo

// ---------------- helpers ----------------
__device__ __forceinline__ uint32_t smem_u32(const void* p) {
    uint32_t a;
    asm("{ .reg .u64 t; cvta.to.shared.u64 t, %1; cvt.u32.u64 %0, t; }" : "=r"(a) : "l"(p));
    return a;
}
__device__ __forceinline__ void cp16(uint32_t dst, const void* src) {
    asm volatile("cp.async.cg.shared.global [%0], [%1], 16;" ::"r"(dst), "l"(src));
}
__device__ __forceinline__ void cp_commit() {
    asm volatile("cp.async.commit_group;" ::: "memory");
}
__device__ __forceinline__ void cp_wait1() {
    asm volatile("cp.async.wait_group 1;" ::: "memory");
}
__device__ __forceinline__ void ldsm4(uint32_t* r, uint32_t addr) {
    asm volatile("ldmatrix.sync.aligned.m8n8.x4.shared.b16 {%0,%1,%2,%3}, [%4];"
                 : "=r"(r[0]), "=r"(r[1]), "=r"(r[2]), "=r"(r[3])
                 : "r"(addr));
}
__device__ __forceinline__ void mma16816(float* d, const uint32_t* a, const uint32_t* b) {
    asm volatile(
        "mma.sync.aligned.m16n8k16.row.col.f32.f16.f16.f32 "
        "{%0,%1,%2,%3}, {%4,%5,%6,%7}, {%8,%9}, {%0,%1,%2,%3};"
        : "+f"(d[0]), "+f"(d[1]), "+f"(d[2]), "+f"(d[3])
        : "r"(a[0]), "r"(a[1]), "r"(a[2]), "r"(a[3]), "r"(b[0]), "r"(b[1]));
}
__device__ __forceinline__ float fast_tanh(float x) {
    float a = fabsf(x);
    float e = exp2f(-2.8853900817779268f * a);
    float r = __fdividef(1.0f - e, 1.0f + e);
    return copysignf(r, x);
}
__device__ __forceinline__ uint32_t pack_h2(float a, float b) {
    __half2 h = __floats2half2_rn(a, b);
    return *(uint32_t*)&h;
}
__device__ __forceinline__ float2 h2f(uint32_t u) {
    __half2 h = *(__half2*)&u;
    return __half22float2(h);
}

// ---------------- kernel 1: sigma ----------------
__global__ void k_sigma(const float* __restrict__ W, const float* __restrict__ u) {
    __shared__ float sv[DH];
    __shared__ float red[DH];
    int t = threadIdx.x;
    float acc = 0.f;
    for (int i = 0; i < DH; i++) acc += W[(size_t)i * DH + t] * u[i];
    sv[t] = acc;
    red[t] = acc * acc;
    __syncthreads();
    for (int s = 256; s > 0; s >>= 1) {
        if (t < s) red[t] += red[t + s];
        __syncthreads();
    }
    float inv1 = 1.f / (sqrtf(red[0]) + 1e-12f);
    __syncthreads();
    sv[t] *= inv1;
    __syncthreads();
    float sacc = 0.f;
    const float* wr = W + (size_t)t * DH;
    for (int j = 0; j < DH; j++) sacc += wr[j] * sv[j];
    red[t] = sacc * sacc;
    __syncthreads();
    for (int s = 256; s > 0; s >>= 1) {
        if (t < s) red[t] += red[t + s];
        __syncthreads();
    }
    if (t == 0) {
        float ss = red[0];
        g_sigma = ss / (sqrtf(ss) + 1e-12f);
    }
}

// ---------------- kernel 2: weight prep ----------------
__global__ void k_prep(const float* __restrict__ W, const float* __restrict__ We,
                       const float* __restrict__ Wh, const float* __restrict__ be,
                       const float* __restrict__ bW) {
    float inv = 1.0f / g_sigma;
    int stride = gridDim.x * blockDim.x;
    int t0 = blockIdx.x * blockDim.x + threadIdx.x;
    for (int idx = t0; idx < DH * DH; idx += stride) {
        float v = W[idx] * inv;
        __half hi = __float2half_rn(v);
        g_whi[idx] = hi;
        g_wlo[idx] = __float2half_rn(v - __half2float(hi));
    }
    for (int idx = t0; idx < DIN * DH; idx += stride) {
        int d = idx >> 9, j = idx & 511;
        g_Wet[idx] = We[(size_t)j * DIN + d];
    }
    for (int idx = t0; idx < DH * DOUT; idx += stride) {
        int k = idx / DOUT, o = idx - k * DOUT;
        g_Wht[idx] = Wh[(size_t)o * DH + k];
    }
    for (int idx = t0; idx < DH; idx += stride) g_bcomb[idx] = be[idx] + bW[idx];
}

// ---------------- generic tiled GEMM ----------------
__global__ __launch_bounds__(256) void k_gemm(const float* __restrict__ A,
                                              const float* __restrict__ Bt,
                                              const float* __restrict__ bias,
                                              float* __restrict__ C, int M, int N, int K) {
    __shared__ float As[16][64];
    __shared__ float Bs[16][64];
    int tid = threadIdx.x;
    int bx = blockIdx.x, by = blockIdx.y;
    int tx = tid & 15, ty = tid >> 4;
    float accv[4][4];
#pragma unroll
    for (int i = 0; i < 4; i++)
#pragma unroll
        for (int j = 0; j < 4; j++) accv[i][j] = 0.f;
    for (int k0 = 0; k0 < K; k0 += 16) {
        {
            int r = tid >> 2;
            int c = (tid & 3) * 4;
            float4 av = *(const float4*)&A[(size_t)(by * 64 + r) * K + k0 + c];
            As[c + 0][r] = av.x;
            As[c + 1][r] = av.y;
            As[c + 2][r] = av.z;
            As[c + 3][r] = av.w;
        }
        {
            int kr = tid >> 4;
            int c = (tid & 15) * 4;
            float4 bv = *(const float4*)&Bt[(size_t)(k0 + kr) * N + bx * 64 + c];
            *(float4*)&Bs[kr][c] = bv;
        }
        __syncthreads();
#pragma unroll
        for (int k = 0; k < 16; k++) {
            float a[4], b[4];
#pragma unroll
            for (int i = 0; i < 4; i++) a[i] = As[k][ty * 4 + i];
#pragma unroll
            for (int j = 0; j < 4; j++) b[j] = Bs[k][tx * 4 + j];
#pragma unroll
            for (int i = 0; i < 4; i++)
#pragma unroll
                for (int j = 0; j < 4; j++) accv[i][j] += a[i] * b[j];
        }
        __syncthreads();
    }
#pragma unroll
    for (int i = 0; i < 4; i++) {
        int m = by * 64 + ty * 4 + i;
#pragma unroll
        for (int j = 0; j < 4; j++) {
            int n = bx * 64 + tx * 4 + j;
            C[(size_t)m * N + n] = accv[i][j] + bias[n];
        }
    }
}

// ---------------- kernel 3: recurrent core (2 CTAs/SM, warp-private W pipe) ----------------
__global__ __launch_bounds__(NT, 2) void k_rec(const int* __restrict__ steps_p) {
    extern __shared__ char smem[];
    const uint32_t sb = smem_u32(smem);
    const int tid = threadIdx.x;
    const int w = tid >> 5, l = tid & 31;
    const int nb = w * 64;  // this warp's private n-range [nb, nb+64)
    const int row0 = blockIdx.x * MROW;
    const uint32_t bbase = sb + B_OFF + (uint32_t)w * BWRP;

    // linear mapping for elementwise phases: row lr (0..31), 64-col block lcb
    const int lr = tid >> 3;
    const int lcb = (tid & 7) * 64;
    const size_t lg = (size_t)(row0 + lr) * DH + lcb;
    const uint32_t la = (uint32_t)(lr * APITCH + lcb * 2);

    // W loader: lane l stages rows l and l+32 of the warp's 64-row slice
    const int r0l = l, r1l = l + 32;
    const __half* srch0 = g_whi + (size_t)(nb + r0l) * DH;
    const __half* srcl0 = g_wlo + (size_t)(nb + r0l) * DH;
    const __half* srch1 = g_whi + (size_t)(nb + r1l) * DH;
    const __half* srcl1 = g_wlo + (size_t)(nb + r1l) * DH;
    const int sw0 = (r0l >> 1) & 3, sw1 = (r1l >> 1) & 3;
    const uint32_t bd0 = (uint32_t)(r0l * BROW), bd1 = (uint32_t)(r1l * BROW);

    // init: h = 0, hxe = xe
#pragma unroll
    for (int q = 0; q < 16; q++) {
        float4 xv = *(const float4*)(g_xe + lg + 4 * q);
        *(float4*)(g_hxe + lg + 4 * q) = xv;
        *(float4*)(g_h + lg + 4 * q) = make_float4(0.f, 0.f, 0.f, 0.f);
    }

    const int steps = steps_p[0];

    for (int s = 0; s < steps; s++) {
        // ---- inner iter 0: hh = 0.5*tanh(hxe) -> smem fp16 ----
#pragma unroll
        for (int q = 0; q < 16; q++) {
            float4 xv = *(const float4*)(g_hxe + lg + 4 * q);
            uint2 hp;
            hp.x = pack_h2(0.5f * fast_tanh(xv.x), 0.5f * fast_tanh(xv.y));
            hp.y = pack_h2(0.5f * fast_tanh(xv.z), 0.5f * fast_tanh(xv.w));
            *(uint2*)(smem + la + 8 * q) = hp;
        }
        __syncthreads();

        // ---- inner iters 1..4 ----
        for (int it = 1; it < 5; it++) {
            float acc[2][8][4];
#pragma unroll
            for (int mt = 0; mt < 2; mt++)
#pragma unroll
                for (int nt = 0; nt < 8; nt++)
#pragma unroll
                    for (int e = 0; e < 4; e++) acc[mt][nt][e] = 0.f;

            // prologue: chunks 0,1 into stages 0,1 (warp-private)
#pragma unroll
            for (int c0 = 0; c0 < 2; c0++) {
                uint32_t st = bbase + (uint32_t)c0 * BSTG;
                cp16(st + bd0 + ((0 ^ sw0) << 4), srch0 + c0 * 16);
                cp16(st + bd0 + ((1 ^ sw0) << 4), srch0 + c0 * 16 + 8);
                cp16(st + bd0 + ((2 ^ sw0) << 4), srcl0 + c0 * 16);
                cp16(st + bd0 + ((3 ^ sw0) << 4), srcl0 + c0 * 16 + 8);
                cp16(st + bd1 + ((0 ^ sw1) << 4), srch1 + c0 * 16);
                cp16(st + bd1 + ((1 ^ sw1) << 4), srch1 + c0 * 16 + 8);
                cp16(st + bd1 + ((2 ^ sw1) << 4), srcl1 + c0 * 16);
                cp16(st + bd1 + ((3 ^ sw1) << 4), srcl1 + c0 * 16 + 8);
                cp_commit();
            }

            for (int c = 0; c < NCHK; c++) {
                cp_wait1();  // own chunk c resident (warp-local)
                const uint32_t stg = bbase + (uint32_t)(c & 1) * BSTG;
                // A fragments: rows mt*16, k = c*16
                uint32_t ah[2][4];
#pragma unroll
                for (int mt = 0; mt < 2; mt++) {
                    uint32_t ao = (uint32_t)((mt * 16 + (l & 15)) * APITCH + c * 32 +
                                             (l >> 4) * 16);
                    ldsm4(ah[mt], sb + ao);
                }
#pragma unroll
                for (int g2 = 0; g2 < 4; g2++) {  // n16 groups
                    int br = g2 * 16 + (l & 7) + 8 * (l >> 4);
                    int sl = (l >> 3) & 1;
                    int bsw = (br >> 1) & 3;
                    uint32_t rowb = stg + (uint32_t)(br * BROW);
                    uint32_t bh[4], bl[4];
                    ldsm4(bh, rowb + (uint32_t)(((sl) ^ bsw) << 4));
                    ldsm4(bl, rowb + (uint32_t)(((sl + 2) ^ bsw) << 4));
#pragma unroll
                    for (int mt = 0; mt < 2; mt++) {
                        mma16816(acc[mt][2 * g2 + 0], ah[mt], bh + 0);
                        mma16816(acc[mt][2 * g2 + 1], ah[mt], bh + 2);
                        mma16816(acc[mt][2 * g2 + 0], ah[mt], bl + 0);
                        mma16816(acc[mt][2 * g2 + 1], ah[mt], bl + 2);
                    }
                }
                // refill chunk c+2 into stage (c&1) AFTER reads (program order safe)
                {
                    int c2 = c + 2;
                    if (c2 < NCHK) {
                        uint32_t st = bbase + (uint32_t)(c & 1) * BSTG;
                        cp16(st + bd0 + ((0 ^ sw0) << 4), srch0 + c2 * 16);
                        cp16(st + bd0 + ((1 ^ sw0) << 4), srch0 + c2 * 16 + 8);
                        cp16(st + bd0 + ((2 ^ sw0) << 4), srcl0 + c2 * 16);
                        cp16(st + bd0 + ((3 ^ sw0) << 4), srcl0 + c2 * 16 + 8);
                        cp16(st + bd1 + ((0 ^ sw1) << 4), srch1 + c2 * 16);
                        cp16(st + bd1 + ((1 ^ sw1) << 4), srch1 + c2 * 16 + 8);
                        cp16(st + bd1 + ((2 ^ sw1) << 4), srcl1 + c2 * 16);
                        cp16(st + bd1 + ((3 ^ sw1) << 4), srcl1 + c2 * 16 + 8);
                    }
                    cp_commit();  // uniform group arithmetic
                }
            }
            __syncthreads();  // all A-smem reads done before epilogue writes

            // ---- epilogue: hh = 0.5*hh_old + 0.5*tanh(acc + hxe) ----
#pragma unroll
            for (int mt = 0; mt < 2; mt++) {
                int ra = mt * 16 + (l >> 2);
#pragma unroll
                for (int half = 0; half < 2; half++) {
                    int r = ra + 8 * half;
                    const size_t gr = (size_t)(row0 + r) * DH;
                    uint32_t aoff = (uint32_t)(r * APITCH);
#pragma unroll
                    for (int nt = 0; nt < 8; nt++) {
                        int col = nb + nt * 8 + 2 * (l & 3);
                        uint32_t hu = *(uint32_t*)(smem + aoff + col * 2);
                        float2 hf = h2f(hu);
                        float2 xe2 = *(const float2*)(g_hxe + gr + col);
                        float a0 = acc[mt][nt][2 * half + 0];
                        float a1 = acc[mt][nt][2 * half + 1];
                        float v0 = 0.5f * hf.x + 0.5f * fast_tanh(a0 + xe2.x);
                        float v1 = 0.5f * hf.y + 0.5f * fast_tanh(a1 + xe2.y);
                        *(uint32_t*)(smem + aoff + col * 2) = pack_h2(v0, v1);
                    }
                }
            }
            __syncthreads();
        }

        // ---- outer update: h = 0.5h + 0.5hh ; hxe = h + xe ----
#pragma unroll
        for (int q = 0; q < 16; q++) {
            uint2 hp = *(uint2*)(smem + la + 8 * q);
            float2 h0 = h2f(hp.x), h1 = h2f(hp.y);
            float4 hv = *(const float4*)(g_h + lg + 4 * q);
            float4 xv = *(const float4*)(g_xe + lg + 4 * q);
            float4 hn;
            hn.x = 0.5f * hv.x + 0.5f * h0.x;
            hn.y = 0.5f * hv.y + 0.5f * h0.y;
            hn.z = 0.5f * hv.z + 0.5f * h1.x;
            hn.w = 0.5f * hv.w + 0.5f * h1.y;
            *(float4*)(g_h + lg + 4 * q) = hn;
            float4 hx;
            hx.x = hn.x + xv.x;
            hx.y = hn.y + xv.y;
            hx.z = hn.z + xv.z;
            hx.w = hn.w + xv.w;
            *(float4*)(g_hxe + lg + 4 * q) = hx;
        }
        __syncthreads();
    }
}

// ---------------- launch ----------------
extern "C" void kernel_launch(void* const* d_in, const int* in_sizes, int n_in, void* d_out,
                              int out_size) {
    const float* x = (const float*)d_in[0];
    const float* We = (const float*)d_in[1];
    const float* be = (const float*)d_in[2];
    const float* W = (const float*)d_in[3];
    const float* bW = (const float*)d_in[4];
    const float* u = (const float*)d_in[5];
    const float* Wh = (const float*)d_in[6];
    const float* bh = (const float*)d_in[7];
    const int* steps = (const int*)d_in[8];
    float* out = (float*)d_out;

    float *p_Wet, *p_Wht, *p_xe, *p_h, *p_bcomb;
    cudaGetSymbolAddress((void**)&p_Wet, g_Wet);
    cudaGetSymbolAddress((void**)&p_Wht, g_Wht);
    cudaGetSymbolAddress((void**)&p_xe, g_xe);
    cudaGetSymbolAddress((void**)&p_h, g_h);
    cudaGetSymbolAddress((void**)&p_bcomb, g_bcomb);

    cudaFuncSetAttribute(k_rec, cudaFuncAttributeMaxDynamicSharedMemorySize, REC_SMEM);

    k_sigma<<<1, 512>>>(W, u);
    k_prep<<<512, 256>>>(W, We, Wh, be, bW);

    dim3 g1(DH / 64, NB / 64);
    k_gemm<<<g1, 256>>>(x, p_Wet, p_bcomb, p_xe, NB, DH, DIN);

    k_rec<<<NCTA, NT, REC_SMEM>>>(steps);

    dim3 g2(DOUT / 64, NB / 64);
    k_gemm<<<g2, 256>>>(p_h, p_Wht, bh, out, NB, DOUT, DH);
}

// round 15
// speedup vs baseline: 1.6083x; 1.6078x over previous
#include <cuda_runtime.h>
#include <cuda_fp16.h>
#include <cstdint>

#define DIN  1024
#define DH   512
#define NB   8192
#define DOUT 512

#define MROW 64
#define NCTA (NB / MROW)   // 128
#define NT   512           // 16 warps
#define NCHK 32            // K/16 chunks per matmul

// A (hh fp16) smem: 64 rows, pitch 1040B (65*16B -> ldmatrix conflict-free)
#define APITCH 1040
#define A_BYTES (MROW * APITCH)          // 66560
// B per-warp stages: 32 rows x 80B (hi k16 @+0..32, lo k16 @+32..64, pad 16)
#define BROW 80
#define BSTG (32 * BROW)                 // 2560 per stage
#define NBSTG 3
#define BWRP (NBSTG * BSTG)              // 7680 per warp
#define B_OFF A_BYTES                    // 66560
#define REC_SMEM (B_OFF + 16 * BWRP)     // 189440

typedef unsigned long long ull;

// ---------------- device scratch ----------------
__device__ float g_sigma;
__device__ __align__(16) float g_Wet[DIN * DH];
__device__ __align__(16) float g_Wht[DH * DOUT];
__device__ __align__(16) float g_bcomb[DH];
__device__ __align__(16) float g_xe[NB * DH];    // x@We.T + be + bW
__device__ __align__(16) float g_hxe[NB * DH];   // h + xe
__device__ __align__(16) float g_h[NB * DH];     // outer state
__device__ __align__(16) __half g_whi[DH * DH];  // (W/sigma)[n][k] fp16 hi
__device__ __align__(16) __half g_wlo[DH * DH];  // fp16 residual lo

// ---------------- helpers ----------------
__device__ __forceinline__ uint32_t smem_u32(const void* p) {
    uint32_t a;
    asm("{ .reg .u64 t; cvta.to.shared.u64 t, %1; cvt.u32.u64 %0, t; }" : "=r"(a) : "l"(p));
    return a;
}
__device__ __forceinline__ void cp16(uint32_t dst, const void* src) {
    asm volatile("cp.async.cg.shared.global [%0], [%1], 16;" ::"r"(dst), "l"(src));
}
__device__ __forceinline__ void cp_commit() {
    asm volatile("cp.async.commit_group;" ::: "memory");
}
__device__ __forceinline__ void cp_wait1() {
    asm volatile("cp.async.wait_group 1;" ::: "memory");
}
__device__ __forceinline__ void ldsm4(uint32_t* r, uint32_t addr) {
    asm volatile("ldmatrix.sync.aligned.m8n8.x4.shared.b16 {%0,%1,%2,%3}, [%4];"
                 : "=r"(r[0]), "=r"(r[1]), "=r"(r[2]), "=r"(r[3])
                 : "r"(addr));
}
__device__ __forceinline__ void mma16816(float* d, const uint32_t* a, const uint32_t* b) {
    asm volatile(
        "mma.sync.aligned.m16n8k16.row.col.f32.f16.f16.f32 "
        "{%0,%1,%2,%3}, {%4,%5,%6,%7}, {%8,%9}, {%0,%1,%2,%3};"
        : "+f"(d[0]), "+f"(d[1]), "+f"(d[2]), "+f"(d[3])
        : "r"(a[0]), "r"(a[1]), "r"(a[2]), "r"(a[3]), "r"(b[0]), "r"(b[1]));
}
__device__ __forceinline__ float fast_tanh(float x) {
    float a = fabsf(x);
    float e = exp2f(-2.8853900817779268f * a);
    float r = __fdividef(1.0f - e, 1.0f + e);
    return copysignf(r, x);
}
__device__ __forceinline__ uint32_t pack_h2(float a, float b) {
    __half2 h = __floats2half2_rn(a, b);
    return *(uint32_t*)&h;
}
__device__ __forceinline__ float2 h2f(uint32_t u) {
    __half2 h = *(__half2*)&u;
    return __half22float2(h);
}

// ---------------- kernel 1: sigma ----------------
__global__ void k_sigma(const float* __restrict__ W, const float* __restrict__ u) {
    __shared__ float sv[DH];
    __shared__ float red[DH];
    int t = threadIdx.x;
    float acc = 0.f;
    for (int i = 0; i < DH; i++) acc += W[(size_t)i * DH + t] * u[i];
    sv[t] = acc;
    red[t] = acc * acc;
    __syncthreads();
    for (int s = 256; s > 0; s >>= 1) {
        if (t < s) red[t] += red[t + s];
        __syncthreads();
    }
    float inv1 = 1.f / (sqrtf(red[0]) + 1e-12f);
    __syncthreads();
    sv[t] *= inv1;
    __syncthreads();
    float sacc = 0.f;
    const float* wr = W + (size_t)t * DH;
    for (int j = 0; j < DH; j++) sacc += wr[j] * sv[j];
    red[t] = sacc * sacc;
    __syncthreads();
    for (int s = 256; s > 0; s >>= 1) {
        if (t < s) red[t] += red[t + s];
        __syncthreads();
    }
    if (t == 0) {
        float ss = red[0];
        g_sigma = ss / (sqrtf(ss) + 1e-12f);
    }
}

// ---------------- kernel 2: weight prep ----------------
__global__ void k_prep(const float* __restrict__ W, const float* __restrict__ We,
                       const float* __restrict__ Wh, const float* __restrict__ be,
                       const float* __restrict__ bW) {
    float inv = 1.0f / g_sigma;
    int stride = gridDim.x * blockDim.x;
    int t0 = blockIdx.x * blockDim.x + threadIdx.x;
    for (int idx = t0; idx < DH * DH; idx += stride) {
        float v = W[idx] * inv;
        __half hi = __float2half_rn(v);
        g_whi[idx] = hi;
        g_wlo[idx] = __float2half_rn(v - __half2float(hi));
    }
    for (int idx = t0; idx < DIN * DH; idx += stride) {
        int d = idx >> 9, j = idx & 511;
        g_Wet[idx] = We[(size_t)j * DIN + d];
    }
    for (int idx = t0; idx < DH * DOUT; idx += stride) {
        int k = idx / DOUT, o = idx - k * DOUT;
        g_Wht[idx] = Wh[(size_t)o * DH + k];
    }
    for (int idx = t0; idx < DH; idx += stride) g_bcomb[idx] = be[idx] + bW[idx];
}

// ---------------- generic tiled GEMM ----------------
__global__ __launch_bounds__(256) void k_gemm(const float* __restrict__ A,
                                              const float* __restrict__ Bt,
                                              const float* __restrict__ bias,
                                              float* __restrict__ C, int M, int N, int K) {
    __shared__ float As[16][64];
    __shared__ float Bs[16][64];
    int tid = threadIdx.x;
    int bx = blockIdx.x, by = blockIdx.y;
    int tx = tid & 15, ty = tid >> 4;
    float accv[4][4];
#pragma unroll
    for (int i = 0; i < 4; i++)
#pragma unroll
        for (int j = 0; j < 4; j++) accv[i][j] = 0.f;
    for (int k0 = 0; k0 < K; k0 += 16) {
        {
            int r = tid >> 2;
            int c = (tid & 3) * 4;
            float4 av = *(const float4*)&A[(size_t)(by * 64 + r) * K + k0 + c];
            As[c + 0][r] = av.x;
            As[c + 1][r] = av.y;
            As[c + 2][r] = av.z;
            As[c + 3][r] = av.w;
        }
        {
            int kr = tid >> 4;
            int c = (tid & 15) * 4;
            float4 bv = *(const float4*)&Bt[(size_t)(k0 + kr) * N + bx * 64 + c];
            *(float4*)&Bs[kr][c] = bv;
        }
        __syncthreads();
#pragma unroll
        for (int k = 0; k < 16; k++) {
            float a[4], b[4];
#pragma unroll
            for (int i = 0; i < 4; i++) a[i] = As[k][ty * 4 + i];
#pragma unroll
            for (int j = 0; j < 4; j++) b[j] = Bs[k][tx * 4 + j];
#pragma unroll
            for (int i = 0; i < 4; i++)
#pragma unroll
                for (int j = 0; j < 4; j++) accv[i][j] += a[i] * b[j];
        }
        __syncthreads();
    }
#pragma unroll
    for (int i = 0; i < 4; i++) {
        int m = by * 64 + ty * 4 + i;
#pragma unroll
        for (int j = 0; j < 4; j++) {
            int n = bx * 64 + tx * 4 + j;
            C[(size_t)m * N + n] = accv[i][j] + bias[n];
        }
    }
}

// ---------------- kernel 3: recurrent core (reordered MMA, warp-private W pipe) ----------------
__global__ __launch_bounds__(NT, 1) void k_rec(const int* __restrict__ steps_p) {
    extern __shared__ char smem[];
    const uint32_t sb = smem_u32(smem);
    const int tid = threadIdx.x;
    const int w = tid >> 5, l = tid & 31;
    const int nb = w * 32;  // this warp's private n-range [nb, nb+32)
    const int row0 = blockIdx.x * MROW;
    const uint32_t bbase = sb + B_OFF + (uint32_t)w * BWRP;

    // linear mapping for elementwise phases: row lr, 64-col block lcb
    const int lr = tid >> 3;
    const int lcb = (tid & 7) * 64;
    const size_t lg = (size_t)(row0 + lr) * DH + lcb;
    const uint32_t la = (uint32_t)(lr * APITCH + lcb * 2);

    // W loader: lane l stages W row (nb + l)
    const __half* srch = g_whi + (size_t)(nb + l) * DH;
    const __half* srcl = g_wlo + (size_t)(nb + l) * DH;
    const uint32_t bdst = (uint32_t)(l * BROW);

    // init: h = 0, hxe = xe
#pragma unroll
    for (int q = 0; q < 16; q++) {
        float4 xv = *(const float4*)(g_xe + lg + 4 * q);
        *(float4*)(g_hxe + lg + 4 * q) = xv;
        *(float4*)(g_h + lg + 4 * q) = make_float4(0.f, 0.f, 0.f, 0.f);
    }

    const int steps = steps_p[0];

    for (int s = 0; s < steps; s++) {
        // ---- inner iter 0: hh = 0.5*tanh(hxe) -> smem fp16 ----
#pragma unroll
        for (int q = 0; q < 16; q++) {
            float4 xv = *(const float4*)(g_hxe + lg + 4 * q);
            uint2 hp;
            hp.x = pack_h2(0.5f * fast_tanh(xv.x), 0.5f * fast_tanh(xv.y));
            hp.y = pack_h2(0.5f * fast_tanh(xv.z), 0.5f * fast_tanh(xv.w));
            *(uint2*)(smem + la + 8 * q) = hp;
        }
        __syncthreads();

        // ---- inner iters 1..4 ----
        for (int it = 1; it < 5; it++) {
            float acc[4][4][4];
#pragma unroll
            for (int mt = 0; mt < 4; mt++)
#pragma unroll
                for (int nt = 0; nt < 4; nt++)
#pragma unroll
                    for (int e = 0; e < 4; e++) acc[mt][nt][e] = 0.f;

            // prologue: chunks 0,1 into stages 0,1 (warp-private)
#pragma unroll
            for (int c0 = 0; c0 < 2; c0++) {
                uint32_t st = bbase + (uint32_t)c0 * BSTG + bdst;
                cp16(st + 0, srch + c0 * 16);
                cp16(st + 16, srch + c0 * 16 + 8);
                cp16(st + 32, srcl + c0 * 16);
                cp16(st + 48, srcl + c0 * 16 + 8);
                cp_commit();
            }

            int stg_idx = 0;  // stage of chunk c
            for (int c = 0; c < NCHK; c++) {
                cp_wait1();  // own chunk c resident (warp-local, no barrier)
                // refill: chunk c+2 into stage (stg_idx+2)%3 (read at c-1, safe)
                {
                    int c2 = c + 2;
                    if (c2 < NCHK) {
                        int s2 = stg_idx + 2;
                        if (s2 >= NBSTG) s2 -= NBSTG;
                        uint32_t st = bbase + (uint32_t)s2 * BSTG + bdst;
                        cp16(st + 0, srch + c2 * 16);
                        cp16(st + 16, srch + c2 * 16 + 8);
                        cp16(st + 32, srcl + c2 * 16);
                        cp16(st + 48, srcl + c2 * 16 + 8);
                    }
                    cp_commit();  // uniform group arithmetic
                }
                const uint32_t stg = bbase + (uint32_t)stg_idx * BSTG;
                // ---- load ALL fragments first ----
                uint32_t ah[4][4];
#pragma unroll
                for (int mt = 0; mt < 4; mt++) {
                    uint32_t ao = (uint32_t)((mt * 16 + (l & 15)) * APITCH + c * 32 +
                                             (l >> 4) * 16);
                    ldsm4(ah[mt], sb + ao);
                }
                uint32_t bh[2][4], bl[2][4];
#pragma unroll
                for (int nt2 = 0; nt2 < 2; nt2++) {
                    uint32_t bo = (uint32_t)((nt2 * 16 + (l & 7) + 8 * (l >> 4)) * BROW +
                                             ((l >> 3) & 1) * 16);
                    ldsm4(bh[nt2], stg + bo);
                    ldsm4(bl[nt2], stg + bo + 32);
                }
                // ---- hi pass: 16 MMAs over 16 distinct accumulators ----
#pragma unroll
                for (int nt2 = 0; nt2 < 2; nt2++)
#pragma unroll
                    for (int mt = 0; mt < 4; mt++) {
                        mma16816(acc[mt][2 * nt2 + 0], ah[mt], bh[nt2] + 0);
                        mma16816(acc[mt][2 * nt2 + 1], ah[mt], bh[nt2] + 2);
                    }
                // ---- lo pass: same accumulators, reuse distance = 16 MMAs ----
#pragma unroll
                for (int nt2 = 0; nt2 < 2; nt2++)
#pragma unroll
                    for (int mt = 0; mt < 4; mt++) {
                        mma16816(acc[mt][2 * nt2 + 0], ah[mt], bl[nt2] + 0);
                        mma16816(acc[mt][2 * nt2 + 1], ah[mt], bl[nt2] + 2);
                    }
                if (++stg_idx == NBSTG) stg_idx = 0;
            }
            __syncthreads();  // all A-smem reads done before epilogue writes

            // ---- epilogue: hh = 0.5*hh_old + 0.5*tanh(acc + hxe) ----
#pragma unroll
            for (int mt = 0; mt < 4; mt++) {
                int ra = mt * 16 + (l >> 2);
#pragma unroll
                for (int half = 0; half < 2; half++) {
                    int r = ra + 8 * half;
                    const size_t gr = (size_t)(row0 + r) * DH;
                    uint32_t aoff = (uint32_t)(r * APITCH);
#pragma unroll
                    for (int nt = 0; nt < 4; nt++) {
                        int col = nb + nt * 8 + 2 * (l & 3);
                        uint32_t hu = *(uint32_t*)(smem + aoff + col * 2);
                        float2 hf = h2f(hu);
                        float2 xe2 = *(const float2*)(g_hxe + gr + col);
                        float a0 = acc[mt][nt][2 * half + 0];
                        float a1 = acc[mt][nt][2 * half + 1];
                        float v0 = 0.5f * hf.x + 0.5f * fast_tanh(a0 + xe2.x);
                        float v1 = 0.5f * hf.y + 0.5f * fast_tanh(a1 + xe2.y);
                        *(uint32_t*)(smem + aoff + col * 2) = pack_h2(v0, v1);
                    }
                }
            }
            __syncthreads();
        }

        // ---- outer update: h = 0.5h + 0.5hh ; hxe = h + xe ----
#pragma unroll
        for (int q = 0; q < 16; q++) {
            uint2 hp = *(uint2*)(smem + la + 8 * q);
            float2 h0 = h2f(hp.x), h1 = h2f(hp.y);
            float4 hv = *(const float4*)(g_h + lg + 4 * q);
            float4 xv = *(const float4*)(g_xe + lg + 4 * q);
            float4 hn;
            hn.x = 0.5f * hv.x + 0.5f * h0.x;
            hn.y = 0.5f * hv.y + 0.5f * h0.y;
            hn.z = 0.5f * hv.z + 0.5f * h1.x;
            hn.w = 0.5f * hv.w + 0.5f * h1.y;
            *(float4*)(g_h + lg + 4 * q) = hn;
            float4 hx;
            hx.x = hn.x + xv.x;
            hx.y = hn.y + xv.y;
            hx.z = hn.z + xv.z;
            hx.w = hn.w + xv.w;
            *(float4*)(g_hxe + lg + 4 * q) = hx;
        }
        __syncthreads();
    }
}

// ---------------- launch ----------------
extern "C" void kernel_launch(void* const* d_in, const int* in_sizes, int n_in, void* d_out,
                              int out_size) {
    const float* x = (const float*)d_in[0];
    const float* We = (const float*)d_in[1];
    const float* be = (const float*)d_in[2];
    const float* W = (const float*)d_in[3];
    const float* bW = (const float*)d_in[4];
    const float* u = (const float*)d_in[5];
    const float* Wh = (const float*)d_in[6];
    const float* bh = (const float*)d_in[7];
    const int* steps = (const int*)d_in[8];
    float* out = (float*)d_out;

    float *p_Wet, *p_Wht, *p_xe, *p_h, *p_bcomb;
    cudaGetSymbolAddress((void**)&p_Wet, g_Wet);
    cudaGetSymbolAddress((void**)&p_Wht, g_Wht);
    cudaGetSymbolAddress((void**)&p_xe, g_xe);
    cudaGetSymbolAddress((void**)&p_h, g_h);
    cudaGetSymbolAddress((void**)&p_bcomb, g_bcomb);

    cudaFuncSetAttribute(k_rec, cudaFuncAttributeMaxDynamicSharedMemorySize, REC_SMEM);

    k_sigma<<<1, 512>>>(W, u);
    k_prep<<<512, 256>>>(W, We, Wh, be, bW);

    dim3 g1(DH / 64, NB / 64);
    k_gemm<<<g1, 256>>>(x, p_Wet, p_bcomb, p_xe, NB, DH, DIN);

    k_rec<<<NCTA, NT, REC_SMEM>>>(steps);

    dim3 g2(DOUT / 64, NB / 64);
    k_gemm<<<g2, 256>>>(p_h, p_Wht, bh, out, NB, DOUT, DH);
}

// round 16
// speedup vs baseline: 1.6084x; 1.0001x over previous
#include <cuda_runtime.h>
#include <cuda_fp16.h>
#include <cstdint>

#define DIN  1024
#define DH   512
#define NB   8192
#define DOUT 512

#define MROW 64
#define NCTA (NB / MROW)   // 128
#define NT   512           // 16 warps
#define NCHK 32            // K/16 chunks per matmul

// A (hh fp16) smem: 64 rows, pitch 1040B (65*16B -> ldmatrix conflict-free)
#define APITCH 1040
#define A_BYTES (MROW * APITCH)          // 66560
// B per-warp stages: 32 rows x 80B (hi k16 @+0..32, lo k16 @+32..64, pad 16)
#define BROW 80
#define BSTG (32 * BROW)                 // 2560 per stage
#define NBSTG 3
#define BWRP (NBSTG * BSTG)              // 7680 per warp
#define B_OFF A_BYTES                    // 66560
#define REC_SMEM (B_OFF + 16 * BWRP)     // 189440

typedef unsigned long long ull;

// ---------------- device scratch ----------------
__device__ float g_sigma;
__device__ __align__(16) float g_Wet[DIN * DH];
__device__ __align__(16) float g_Wht[DH * DOUT];
__device__ __align__(16) float g_bcomb[DH];
__device__ __align__(16) float g_xe[NB * DH];    // x@We.T + be + bW
__device__ __align__(16) float g_hxe[NB * DH];   // h + xe
__device__ __align__(16) float g_h[NB * DH];     // outer state
__device__ __align__(16) __half g_whi[DH * DH];  // (W/sigma)[n][k] fp16 hi
__device__ __align__(16) __half g_wlo[DH * DH];  // fp16 residual lo

// ---------------- helpers ----------------
__device__ __forceinline__ uint32_t smem_u32(const void* p) {
    uint32_t a;
    asm("{ .reg .u64 t; cvta.to.shared.u64 t, %1; cvt.u32.u64 %0, t; }" : "=r"(a) : "l"(p));
    return a;
}
__device__ __forceinline__ void cp16(uint32_t dst, const void* src) {
    asm volatile("cp.async.cg.shared.global [%0], [%1], 16;" ::"r"(dst), "l"(src));
}
__device__ __forceinline__ void cp_commit() {
    asm volatile("cp.async.commit_group;" ::: "memory");
}
__device__ __forceinline__ void cp_wait1() {
    asm volatile("cp.async.wait_group 1;" ::: "memory");
}
__device__ __forceinline__ void ldsm4(uint32_t* r, uint32_t addr) {
    asm volatile("ldmatrix.sync.aligned.m8n8.x4.shared.b16 {%0,%1,%2,%3}, [%4];"
                 : "=r"(r[0]), "=r"(r[1]), "=r"(r[2]), "=r"(r[3])
                 : "r"(addr));
}
__device__ __forceinline__ void mma16816(float* d, const uint32_t* a, const uint32_t* b) {
    asm volatile(
        "mma.sync.aligned.m16n8k16.row.col.f32.f16.f16.f32 "
        "{%0,%1,%2,%3}, {%4,%5,%6,%7}, {%8,%9}, {%0,%1,%2,%3};"
        : "+f"(d[0]), "+f"(d[1]), "+f"(d[2]), "+f"(d[3])
        : "r"(a[0]), "r"(a[1]), "r"(a[2]), "r"(a[3]), "r"(b[0]), "r"(b[1]));
}
__device__ __forceinline__ float fast_tanh(float x) {
    float a = fabsf(x);
    float e = exp2f(-2.8853900817779268f * a);
    float r = __fdividef(1.0f - e, 1.0f + e);
    return copysignf(r, x);
}
__device__ __forceinline__ uint32_t pack_h2(float a, float b) {
    __half2 h = __floats2half2_rn(a, b);
    return *(uint32_t*)&h;
}
__device__ __forceinline__ float2 h2f(uint32_t u) {
    __half2 h = *(__half2*)&u;
    return __half22float2(h);
}

// ---------------- kernel 1: sigma ----------------
__global__ void k_sigma(const float* __restrict__ W, const float* __restrict__ u) {
    __shared__ float sv[DH];
    __shared__ float red[DH];
    int t = threadIdx.x;
    float acc = 0.f;
    for (int i = 0; i < DH; i++) acc += W[(size_t)i * DH + t] * u[i];
    sv[t] = acc;
    red[t] = acc * acc;
    __syncthreads();
    for (int s = 256; s > 0; s >>= 1) {
        if (t < s) red[t] += red[t + s];
        __syncthreads();
    }
    float inv1 = 1.f / (sqrtf(red[0]) + 1e-12f);
    __syncthreads();
    sv[t] *= inv1;
    __syncthreads();
    float sacc = 0.f;
    const float* wr = W + (size_t)t * DH;
    for (int j = 0; j < DH; j++) sacc += wr[j] * sv[j];
    red[t] = sacc * sacc;
    __syncthreads();
    for (int s = 256; s > 0; s >>= 1) {
        if (t < s) red[t] += red[t + s];
        __syncthreads();
    }
    if (t == 0) {
        float ss = red[0];
        g_sigma = ss / (sqrtf(ss) + 1e-12f);
    }
}

// ---------------- kernel 2: weight prep ----------------
__global__ void k_prep(const float* __restrict__ W, const float* __restrict__ We,
                       const float* __restrict__ Wh, const float* __restrict__ be,
                       const float* __restrict__ bW) {
    float inv = 1.0f / g_sigma;
    int stride = gridDim.x * blockDim.x;
    int t0 = blockIdx.x * blockDim.x + threadIdx.x;
    for (int idx = t0; idx < DH * DH; idx += stride) {
        float v = W[idx] * inv;
        __half hi = __float2half_rn(v);
        g_whi[idx] = hi;
        g_wlo[idx] = __float2half_rn(v - __half2float(hi));
    }
    for (int idx = t0; idx < DIN * DH; idx += stride) {
        int d = idx >> 9, j = idx & 511;
        g_Wet[idx] = We[(size_t)j * DIN + d];
    }
    for (int idx = t0; idx < DH * DOUT; idx += stride) {
        int k = idx / DOUT, o = idx - k * DOUT;
        g_Wht[idx] = Wh[(size_t)o * DH + k];
    }
    for (int idx = t0; idx < DH; idx += stride) g_bcomb[idx] = be[idx] + bW[idx];
}

// ---------------- generic tiled GEMM ----------------
__global__ __launch_bounds__(256) void k_gemm(const float* __restrict__ A,
                                              const float* __restrict__ Bt,
                                              const float* __restrict__ bias,
                                              float* __restrict__ C, int M, int N, int K) {
    __shared__ float As[16][64];
    __shared__ float Bs[16][64];
    int tid = threadIdx.x;
    int bx = blockIdx.x, by = blockIdx.y;
    int tx = tid & 15, ty = tid >> 4;
    float accv[4][4];
#pragma unroll
    for (int i = 0; i < 4; i++)
#pragma unroll
        for (int j = 0; j < 4; j++) accv[i][j] = 0.f;
    for (int k0 = 0; k0 < K; k0 += 16) {
        {
            int r = tid >> 2;
            int c = (tid & 3) * 4;
            float4 av = *(const float4*)&A[(size_t)(by * 64 + r) * K + k0 + c];
            As[c + 0][r] = av.x;
            As[c + 1][r] = av.y;
            As[c + 2][r] = av.z;
            As[c + 3][r] = av.w;
        }
        {
            int kr = tid >> 4;
            int c = (tid & 15) * 4;
            float4 bv = *(const float4*)&Bt[(size_t)(k0 + kr) * N + bx * 64 + c];
            *(float4*)&Bs[kr][c] = bv;
        }
        __syncthreads();
#pragma unroll
        for (int k = 0; k < 16; k++) {
            float a[4], b[4];
#pragma unroll
            for (int i = 0; i < 4; i++) a[i] = As[k][ty * 4 + i];
#pragma unroll
            for (int j = 0; j < 4; j++) b[j] = Bs[k][tx * 4 + j];
#pragma unroll
            for (int i = 0; i < 4; i++)
#pragma unroll
                for (int j = 0; j < 4; j++) accv[i][j] += a[i] * b[j];
        }
        __syncthreads();
    }
#pragma unroll
    for (int i = 0; i < 4; i++) {
        int m = by * 64 + ty * 4 + i;
#pragma unroll
        for (int j = 0; j < 4; j++) {
            int n = bx * 64 + tx * 4 + j;
            C[(size_t)m * N + n] = accv[i][j] + bias[n];
        }
    }
}

// ---------------- kernel 3: recurrent core (reordered MMA, warp-private W pipe) ----------------
__global__ __launch_bounds__(NT, 1) void k_rec(const int* __restrict__ steps_p) {
    extern __shared__ char smem[];
    const uint32_t sb = smem_u32(smem);
    const int tid = threadIdx.x;
    const int w = tid >> 5, l = tid & 31;
    const int nb = w * 32;  // this warp's private n-range [nb, nb+32)
    const int row0 = blockIdx.x * MROW;
    const uint32_t bbase = sb + B_OFF + (uint32_t)w * BWRP;

    // linear mapping for elementwise phases: row lr, 64-col block lcb
    const int lr = tid >> 3;
    const int lcb = (tid & 7) * 64;
    const size_t lg = (size_t)(row0 + lr) * DH + lcb;
    const uint32_t la = (uint32_t)(lr * APITCH + lcb * 2);

    // W loader: lane l stages W row (nb + l)
    const __half* srch = g_whi + (size_t)(nb + l) * DH;
    const __half* srcl = g_wlo + (size_t)(nb + l) * DH;
    const uint32_t bdst = (uint32_t)(l * BROW);

    // init: h = 0, hxe = xe
#pragma unroll
    for (int q = 0; q < 16; q++) {
        float4 xv = *(const float4*)(g_xe + lg + 4 * q);
        *(float4*)(g_hxe + lg + 4 * q) = xv;
        *(float4*)(g_h + lg + 4 * q) = make_float4(0.f, 0.f, 0.f, 0.f);
    }

    const int steps = steps_p[0];

    for (int s = 0; s < steps; s++) {
        // ---- inner iter 0: hh = 0.5*tanh(hxe) -> smem fp16 ----
#pragma unroll
        for (int q = 0; q < 16; q++) {
            float4 xv = *(const float4*)(g_hxe + lg + 4 * q);
            uint2 hp;
            hp.x = pack_h2(0.5f * fast_tanh(xv.x), 0.5f * fast_tanh(xv.y));
            hp.y = pack_h2(0.5f * fast_tanh(xv.z), 0.5f * fast_tanh(xv.w));
            *(uint2*)(smem + la + 8 * q) = hp;
        }
        __syncthreads();

        // ---- inner iters 1..4 ----
        for (int it = 1; it < 5; it++) {
            float acc[4][4][4];
#pragma unroll
            for (int mt = 0; mt < 4; mt++)
#pragma unroll
                for (int nt = 0; nt < 4; nt++)
#pragma unroll
                    for (int e = 0; e < 4; e++) acc[mt][nt][e] = 0.f;

            // prologue: chunks 0,1 into stages 0,1 (warp-private)
#pragma unroll
            for (int c0 = 0; c0 < 2; c0++) {
                uint32_t st = bbase + (uint32_t)c0 * BSTG + bdst;
                cp16(st + 0, srch + c0 * 16);
                cp16(st + 16, srch + c0 * 16 + 8);
                cp16(st + 32, srcl + c0 * 16);
                cp16(st + 48, srcl + c0 * 16 + 8);
                cp_commit();
            }

            int stg_idx = 0;  // stage of chunk c
            for (int c = 0; c < NCHK; c++) {
                cp_wait1();  // own chunk c resident (warp-local, no barrier)
                // refill: chunk c+2 into stage (stg_idx+2)%3 (read at c-1, safe)
                {
                    int c2 = c + 2;
                    if (c2 < NCHK) {
                        int s2 = stg_idx + 2;
                        if (s2 >= NBSTG) s2 -= NBSTG;
                        uint32_t st = bbase + (uint32_t)s2 * BSTG + bdst;
                        cp16(st + 0, srch + c2 * 16);
                        cp16(st + 16, srch + c2 * 16 + 8);
                        cp16(st + 32, srcl + c2 * 16);
                        cp16(st + 48, srcl + c2 * 16 + 8);
                    }
                    cp_commit();  // uniform group arithmetic
                }
                const uint32_t stg = bbase + (uint32_t)stg_idx * BSTG;
                // ---- load ALL fragments first ----
                uint32_t ah[4][4];
#pragma unroll
                for (int mt = 0; mt < 4; mt++) {
                    uint32_t ao = (uint32_t)((mt * 16 + (l & 15)) * APITCH + c * 32 +
                                             (l >> 4) * 16);
                    ldsm4(ah[mt], sb + ao);
                }
                uint32_t bh[2][4], bl[2][4];
#pragma unroll
                for (int nt2 = 0; nt2 < 2; nt2++) {
                    uint32_t bo = (uint32_t)((nt2 * 16 + (l & 7) + 8 * (l >> 4)) * BROW +
                                             ((l >> 3) & 1) * 16);
                    ldsm4(bh[nt2], stg + bo);
                    ldsm4(bl[nt2], stg + bo + 32);
                }
                // ---- hi pass: 16 MMAs over 16 distinct accumulators ----
#pragma unroll
                for (int nt2 = 0; nt2 < 2; nt2++)
#pragma unroll
                    for (int mt = 0; mt < 4; mt++) {
                        mma16816(acc[mt][2 * nt2 + 0], ah[mt], bh[nt2] + 0);
                        mma16816(acc[mt][2 * nt2 + 1], ah[mt], bh[nt2] + 2);
                    }
                // ---- lo pass: same accumulators, reuse distance = 16 MMAs ----
#pragma unroll
                for (int nt2 = 0; nt2 < 2; nt2++)
#pragma unroll
                    for (int mt = 0; mt < 4; mt++) {
                        mma16816(acc[mt][2 * nt2 + 0], ah[mt], bl[nt2] + 0);
                        mma16816(acc[mt][2 * nt2 + 1], ah[mt], bl[nt2] + 2);
                    }
                if (++stg_idx == NBSTG) stg_idx = 0;
            }
            __syncthreads();  // all A-smem reads done before epilogue writes

            // ---- epilogue: hh = 0.5*hh_old + 0.5*tanh(acc + hxe) ----
#pragma unroll
            for (int mt = 0; mt < 4; mt++) {
                int ra = mt * 16 + (l >> 2);
#pragma unroll
                for (int half = 0; half < 2; half++) {
                    int r = ra + 8 * half;
                    const size_t gr = (size_t)(row0 + r) * DH;
                    uint32_t aoff = (uint32_t)(r * APITCH);
#pragma unroll
                    for (int nt = 0; nt < 4; nt++) {
                        int col = nb + nt * 8 + 2 * (l & 3);
                        uint32_t hu = *(uint32_t*)(smem + aoff + col * 2);
                        float2 hf = h2f(hu);
                        float2 xe2 = *(const float2*)(g_hxe + gr + col);
                        float a0 = acc[mt][nt][2 * half + 0];
                        float a1 = acc[mt][nt][2 * half + 1];
                        float v0 = 0.5f * hf.x + 0.5f * fast_tanh(a0 + xe2.x);
                        float v1 = 0.5f * hf.y + 0.5f * fast_tanh(a1 + xe2.y);
                        *(uint32_t*)(smem + aoff + col * 2) = pack_h2(v0, v1);
                    }
                }
            }
            __syncthreads();
        }

        // ---- outer update: h = 0.5h + 0.5hh ; hxe = h + xe ----
#pragma unroll
        for (int q = 0; q < 16; q++) {
            uint2 hp = *(uint2*)(smem + la + 8 * q);
            float2 h0 = h2f(hp.x), h1 = h2f(hp.y);
            float4 hv = *(const float4*)(g_h + lg + 4 * q);
            float4 xv = *(const float4*)(g_xe + lg + 4 * q);
            float4 hn;
            hn.x = 0.5f * hv.x + 0.5f * h0.x;
            hn.y = 0.5f * hv.y + 0.5f * h0.y;
            hn.z = 0.5f * hv.z + 0.5f * h1.x;
            hn.w = 0.5f * hv.w + 0.5f * h1.y;
            *(float4*)(g_h + lg + 4 * q) = hn;
            float4 hx;
            hx.x = hn.x + xv.x;
            hx.y = hn.y + xv.y;
            hx.z = hn.z + xv.z;
            hx.w = hn.w + xv.w;
            *(float4*)(g_hxe + lg + 4 * q) = hx;
        }
        __syncthreads();
    }
}

// ---------------- launch ----------------
extern "C" void kernel_launch(void* const* d_in, const int* in_sizes, int n_in, void* d_out,
                              int out_size) {
    const float* x = (const float*)d_in[0];
    const float* We = (const float*)d_in[1];
    const float* be = (const float*)d_in[2];
    const float* W = (const float*)d_in[3];
    const float* bW = (const float*)d_in[4];
    const float* u = (const float*)d_in[5];
    const float* Wh = (const float*)d_in[6];
    const float* bh = (const float*)d_in[7];
    const int* steps = (const int*)d_in[8];
    float* out = (float*)d_out;

    float *p_Wet, *p_Wht, *p_xe, *p_h, *p_bcomb;
    cudaGetSymbolAddress((void**)&p_Wet, g_Wet);
    cudaGetSymbolAddress((void**)&p_Wht, g_Wht);
    cudaGetSymbolAddress((void**)&p_xe, g_xe);
    cudaGetSymbolAddress((void**)&p_h, g_h);
    cudaGetSymbolAddress((void**)&p_bcomb, g_bcomb);

    cudaFuncSetAttribute(k_rec, cudaFuncAttributeMaxDynamicSharedMemorySize, REC_SMEM);

    k_sigma<<<1, 512>>>(W, u);
    k_prep<<<512, 256>>>(W, We, Wh, be, bW);

    dim3 g1(DH / 64, NB / 64);
    k_gemm<<<g1, 256>>>(x, p_Wet, p_bcomb, p_xe, NB, DH, DIN);

    k_rec<<<NCTA, NT, REC_SMEM>>>(steps);

    dim3 g2(DOUT / 64, NB / 64);
    k_gemm<<<g2, 256>>>(p_h, p_Wht, bh, out, NB, DOUT, DH);
}